// round 14
// baseline (speedup 1.0000x reference)
#include <cuda_runtime.h>
#include <cuda_bf16.h>
#include <math.h>
#include <stdint.h>

#define N 16384
#define D 1024
#define BT 128            // block tile (M and N)
#define BK 64             // k-chunk in bf16 (=128 bytes per row)
#define NKT (D / BK)      // 16
#define NSTAGE 3
#define NTILES 8256       // 128*129/2 upper-triangular tiles

// ---------------- device globals ----------------
__device__ __align__(128) __nv_bfloat16 g_bf[(size_t)N * D];
__device__ unsigned g_rowmax[N];
__device__ float g_part[64];
__device__ unsigned g_done;       // zero-initialized; self-resetting

__device__ __forceinline__ unsigned f2key(float f) {
    unsigned u = __float_as_uint(f);
    return (u & 0x80000000u) ? ~u : (u | 0x80000000u);
}
__device__ __forceinline__ float key2f(unsigned k) {
    unsigned u = (k & 0x80000000u) ? (k & 0x7FFFFFFFu) : ~k;
    return __uint_as_float(u);
}

__device__ __forceinline__ uint32_t smem_u32(const void* p) {
    uint32_t a;
    asm("{ .reg .u64 t; cvta.to.shared.u64 t, %1; cvt.u32.u64 %0, t; }" : "=r"(a) : "l"(p));
    return a;
}
#define SW128(off) ((off) ^ (((off) >> 3) & 0x70))

__device__ __forceinline__ void cp16(uint32_t dst, const void* src) {
    asm volatile("cp.async.cg.shared.global [%0], [%1], 16;" :: "r"(dst), "l"(src));
}

__device__ __forceinline__ void ldm_x4(uint32_t* r, uint32_t addr) {
    asm volatile("ldmatrix.sync.aligned.m8n8.x4.shared.b16 {%0,%1,%2,%3}, [%4];"
                 : "=r"(r[0]), "=r"(r[1]), "=r"(r[2]), "=r"(r[3]) : "r"(addr));
}

__device__ __forceinline__ void mma16816(float* c, const uint32_t* a, const uint32_t* b) {
    asm volatile(
        "mma.sync.aligned.m16n8k16.row.col.f32.bf16.bf16.f32 "
        "{%0,%1,%2,%3}, {%4,%5,%6,%7}, {%8,%9}, {%0,%1,%2,%3};"
        : "+f"(c[0]), "+f"(c[1]), "+f"(c[2]), "+f"(c[3])
        : "r"(a[0]), "r"(a[1]), "r"(a[2]), "r"(a[3]), "r"(b[0]), "r"(b[1]));
}

// ---------------- kernel 1: L2-normalize rows -> bf16 (+ rowmax init) ----------------
__global__ void normalize_kernel(const float* __restrict__ in) {
    int row = blockIdx.x;
    if (threadIdx.x == 0) g_rowmax[row] = 0u;
    float4 v = ((const float4*)(in + (size_t)row * D))[threadIdx.x];
    float s = v.x * v.x + v.y * v.y + v.z * v.z + v.w * v.w;
    __shared__ float red[8];
    #pragma unroll
    for (int o = 16; o > 0; o >>= 1) s += __shfl_xor_sync(0xffffffffu, s, o);
    if ((threadIdx.x & 31) == 0) red[threadIdx.x >> 5] = s;
    __syncthreads();
    if (threadIdx.x < 8) {
        float t = red[threadIdx.x];
        #pragma unroll
        for (int o = 4; o > 0; o >>= 1) t += __shfl_xor_sync(0xffu, t, o);
        if (threadIdx.x == 0) red[0] = t;
    }
    __syncthreads();
    float scale = 1.0f / fmaxf(sqrtf(red[0]), 1e-12f);
    __nv_bfloat162 p0 = __nv_bfloat162(__float2bfloat16(v.x * scale), __float2bfloat16(v.y * scale));
    __nv_bfloat162 p1 = __nv_bfloat162(__float2bfloat16(v.z * scale), __float2bfloat16(v.w * scale));
    size_t base = (size_t)row * D + threadIdx.x * 4;
    ((__nv_bfloat162*)(g_bf + base))[0] = p0;
    ((__nv_bfloat162*)(g_bf + base))[1] = p1;
}

// ---------------- kernel 2: 128x128 gram tile, flattened triangular grid ----------------
#define A_OFF 0
#define B_OFF 16384
#define STAGE_BYTES 32768
#define SMEM_TOTAL (NSTAGE * STAGE_BYTES)

__global__ void __launch_bounds__(256, 2) gram_kernel() {
    // decode linear tile id -> (ti, tj), ti <= tj, row ti has 128-ti tiles
    int t = blockIdx.x;
    int ti = (int)((257.0 - sqrt(257.0 * 257.0 - 8.0 * (double)t)) * 0.5);
    while (ti * (257 - ti) / 2 > t) ti--;
    while ((ti + 1) * (256 - ti) / 2 <= t) ti++;
    int tj = ti + (t - ti * (257 - ti) / 2);

    extern __shared__ char smem[];
    __shared__ unsigned s_rmax[BT], s_cmax[BT];

    const int rowBase = ti * BT;
    const int colBase = tj * BT;
    const int tid  = threadIdx.x;
    const int lane = tid & 31;
    const int wid  = tid >> 5;       // 0..7
    const int wm   = wid & 3;        // rows wm*32..+31
    const int wn   = wid >> 2;       // cols wn*64..+63

    if (tid < BT) { s_rmax[tid] = 0u; s_cmax[tid] = 0u; }

    uint32_t sb = smem_u32(smem);

    auto load_stage = [&](int kt, int s) {
        int k0 = kt * BK;
        uint32_t base = sb + s * STAGE_BYTES;
        #pragma unroll
        for (int it = 0; it < 4; it++) {
            int i = tid + it * 256;                        // 0..1023
            int r = i >> 3, seg = i & 7;
            uint32_t off = SW128(r * 128 + seg * 16);
            cp16(base + A_OFF + off, g_bf + (size_t)(rowBase + r) * D + k0 + seg * 8);
            cp16(base + B_OFF + off, g_bf + (size_t)(colBase + r) * D + k0 + seg * 8);
        }
        asm volatile("cp.async.commit_group;" ::: "memory");
    };

    float acc[2][8][4];
    #pragma unroll
    for (int mf = 0; mf < 2; mf++)
        #pragma unroll
        for (int nf = 0; nf < 8; nf++)
            #pragma unroll
            for (int e = 0; e < 4; e++) acc[mf][nf][e] = 0.0f;

    const int aRowL = (lane & 7) + ((lane >> 3) & 1) * 8;
    const int aColS = (lane >> 4) * 16;
    const int bRowL = (lane & 7) + (lane >> 4) * 8;
    const int bColS = ((lane >> 3) & 1) * 16;

    load_stage(0, 0);
    load_stage(1, 1);

    #pragma unroll 1
    for (int kt = 0; kt < NKT; kt++) {
        int s = kt % NSTAGE;
        if (kt == NKT - 1) asm volatile("cp.async.wait_group 0;" ::: "memory");
        else               asm volatile("cp.async.wait_group 1;" ::: "memory");
        __syncthreads();   // load kt visible; all warps past compute of kt-1
        if (kt + 2 < NKT) load_stage(kt + 2, (kt + 2) % NSTAGE);

        uint32_t aBase = sb + s * STAGE_BYTES + A_OFF;
        uint32_t bBase = sb + s * STAGE_BYTES + B_OFF;

        #pragma unroll
        for (int ks = 0; ks < 4; ks++) {
            int kb = ks * 32;
            uint32_t a[2][4], b[4][4];
            #pragma unroll
            for (int mf = 0; mf < 2; mf++) {
                int r = wm * 32 + mf * 16 + aRowL;
                ldm_x4(a[mf], aBase + SW128(r * 128 + kb + aColS));
            }
            #pragma unroll
            for (int np = 0; np < 4; np++) {
                int r = wn * 64 + np * 16 + bRowL;
                ldm_x4(b[np], bBase + SW128(r * 128 + kb + bColS));
            }
            #pragma unroll
            for (int mf = 0; mf < 2; mf++)
                #pragma unroll
                for (int np = 0; np < 4; np++) {
                    mma16816(acc[mf][2 * np],     a[mf], &b[np][0]);
                    mma16816(acc[mf][2 * np + 1], a[mf], &b[np][2]);
                }
        }
    }

    // ---- diagonal mask ----
    const int g  = lane >> 2;
    const int cq = lane & 3;
    if (ti == tj) {
        #pragma unroll
        for (int mf = 0; mf < 2; mf++)
            #pragma unroll
            for (int nf = 0; nf < 8; nf++)
                #pragma unroll
                for (int e = 0; e < 4; e++) {
                    int row = wm * 32 + mf * 16 + g + (e >> 1) * 8;
                    int col = wn * 64 + nf * 8 + 2 * cq + (e & 1);
                    if (row == col) acc[mf][nf][e] = -3.0f;
                }
    }

    // ---- row maxes ----
    #pragma unroll
    for (int mf = 0; mf < 2; mf++)
        #pragma unroll
        for (int h = 0; h < 2; h++) {
            float m = -3.0f;
            #pragma unroll
            for (int nf = 0; nf < 8; nf++) {
                m = fmaxf(m, acc[mf][nf][2 * h]);
                m = fmaxf(m, acc[mf][nf][2 * h + 1]);
            }
            m = fmaxf(m, __shfl_xor_sync(0xffffffffu, m, 1));
            m = fmaxf(m, __shfl_xor_sync(0xffffffffu, m, 2));
            if (cq == 0) atomicMax(&s_rmax[wm * 32 + mf * 16 + h * 8 + g], f2key(m));
        }

    // ---- col maxes ----
    #pragma unroll
    for (int nf = 0; nf < 8; nf++)
        #pragma unroll
        for (int e = 0; e < 2; e++) {
            float m = -3.0f;
            #pragma unroll
            for (int mf = 0; mf < 2; mf++) {
                m = fmaxf(m, acc[mf][nf][e]);
                m = fmaxf(m, acc[mf][nf][2 + e]);
            }
            m = fmaxf(m, __shfl_xor_sync(0xffffffffu, m, 4));
            m = fmaxf(m, __shfl_xor_sync(0xffffffffu, m, 8));
            m = fmaxf(m, __shfl_xor_sync(0xffffffffu, m, 16));
            if (g == 0) atomicMax(&s_cmax[wn * 64 + nf * 8 + 2 * cq + e], f2key(m));
        }
    __syncthreads();

    if (tid < BT) {
        atomicMax(&g_rowmax[rowBase + tid], s_rmax[tid]);
    } else {
        int c = tid - BT;
        if (ti != tj) atomicMax(&g_rowmax[colBase + c], s_cmax[c]);
    }
}

// ---------------- kernel 3: fused loss (64 blocks; last block finalizes) ----------------
__global__ void loss_kernel(float* __restrict__ out) {
    int i = blockIdx.x * 256 + threadIdx.x;      // one element per thread
    float md = key2f(g_rowmax[i]);
    float d2 = fmaxf(2.0f - 2.0f * md, 0.0f);
    float s  = logf(sqrtf(d2) + 1e-8f);
    __shared__ float red[8];
    __shared__ bool amLast;
    #pragma unroll
    for (int o = 16; o > 0; o >>= 1) s += __shfl_xor_sync(0xffffffffu, s, o);
    if ((threadIdx.x & 31) == 0) red[threadIdx.x >> 5] = s;
    __syncthreads();
    if (threadIdx.x < 8) {
        float t = red[threadIdx.x];
        #pragma unroll
        for (int o = 4; o > 0; o >>= 1) t += __shfl_xor_sync(0xffu, t, o);
        if (threadIdx.x == 0) {
            g_part[blockIdx.x] = t;
            __threadfence();
            unsigned prev = atomicInc(&g_done, 63u);   // wraps 63 -> 0 (self-reset)
            amLast = (prev == 63u);
        }
    }
    __syncthreads();
    if (amLast && threadIdx.x < 64) {
        float v = g_part[threadIdx.x];
        #pragma unroll
        for (int o = 16; o > 0; o >>= 1) v += __shfl_xor_sync(0xffffffffu, v, o);
        __shared__ float fin[2];
        if ((threadIdx.x & 31) == 0) fin[threadIdx.x >> 5] = v;
        __syncwarp();
        if (threadIdx.x == 32) {                       // warp1 lane0 writes after its shuffle
            // handled below by thread 0 via fin[]
        }
        __syncthreads();
        if (threadIdx.x == 0) out[0] = -(fin[0] + fin[1]) / (float)N;
    }
}

// ---------------- launch ----------------
extern "C" void kernel_launch(void* const* d_in, const int* in_sizes, int n_in,
                              void* d_out, int out_size) {
    const float* feats = (const float*)d_in[0];
    float* out = (float*)d_out;

    cudaFuncSetAttribute(gram_kernel, cudaFuncAttributeMaxDynamicSharedMemorySize, SMEM_TOTAL);

    normalize_kernel<<<N, 256>>>(feats);
    gram_kernel<<<NTILES, 256, SMEM_TOTAL>>>();
    loss_kernel<<<64, 256>>>(out);
}

// round 15
// speedup vs baseline: 1.0156x; 1.0156x over previous
#include <cuda_runtime.h>
#include <cuda_bf16.h>
#include <math.h>
#include <stdint.h>

#define N 16384
#define D 1024
#define BT 128            // block tile (M and N)
#define BK 64             // k-chunk in bf16 (=128 bytes per row)
#define NKT (D / BK)      // 16
#define NSTAGE 3

// ---------------- device globals ----------------
__device__ __align__(128) __nv_bfloat16 g_bf[(size_t)N * D];
__device__ unsigned g_rowmax[N];
__device__ float g_part[64];

__device__ __forceinline__ unsigned f2key(float f) {
    unsigned u = __float_as_uint(f);
    return (u & 0x80000000u) ? ~u : (u | 0x80000000u);
}
__device__ __forceinline__ float key2f(unsigned k) {
    unsigned u = (k & 0x80000000u) ? (k & 0x7FFFFFFFu) : ~k;
    return __uint_as_float(u);
}

__device__ __forceinline__ uint32_t smem_u32(const void* p) {
    uint32_t a;
    asm("{ .reg .u64 t; cvta.to.shared.u64 t, %1; cvt.u32.u64 %0, t; }" : "=r"(a) : "l"(p));
    return a;
}
#define SW128(off) ((off) ^ (((off) >> 3) & 0x70))

__device__ __forceinline__ void cp16(uint32_t dst, const void* src) {
    asm volatile("cp.async.cg.shared.global [%0], [%1], 16;" :: "r"(dst), "l"(src));
}

__device__ __forceinline__ void ldm_x4(uint32_t* r, uint32_t addr) {
    asm volatile("ldmatrix.sync.aligned.m8n8.x4.shared.b16 {%0,%1,%2,%3}, [%4];"
                 : "=r"(r[0]), "=r"(r[1]), "=r"(r[2]), "=r"(r[3]) : "r"(addr));
}

__device__ __forceinline__ void mma16816(float* c, const uint32_t* a, const uint32_t* b) {
    asm volatile(
        "mma.sync.aligned.m16n8k16.row.col.f32.bf16.bf16.f32 "
        "{%0,%1,%2,%3}, {%4,%5,%6,%7}, {%8,%9}, {%0,%1,%2,%3};"
        : "+f"(c[0]), "+f"(c[1]), "+f"(c[2]), "+f"(c[3])
        : "r"(a[0]), "r"(a[1]), "r"(a[2]), "r"(a[3]), "r"(b[0]), "r"(b[1]));
}

// ---------------- kernel 1: warp-per-row L2-normalize -> bf16 (+ rowmax init) ----------------
// 256 thr = 8 warps = 8 rows/block; no smem, no block barrier.
__global__ void __launch_bounds__(256) normalize_kernel(const float* __restrict__ in) {
    int warp = threadIdx.x >> 5;
    int lane = threadIdx.x & 31;
    int row  = blockIdx.x * 8 + warp;
    if (lane == 0) g_rowmax[row] = 0u;

    const float4* src = (const float4*)(in + (size_t)row * D);
    float4 v[8];
    float s = 0.0f;
    #pragma unroll
    for (int i = 0; i < 8; i++) {
        v[i] = src[lane + 32 * i];
        s += v[i].x * v[i].x + v[i].y * v[i].y + v[i].z * v[i].z + v[i].w * v[i].w;
    }
    #pragma unroll
    for (int o = 16; o > 0; o >>= 1) s += __shfl_xor_sync(0xffffffffu, s, o);

    float scale = 1.0f / fmaxf(sqrtf(s), 1e-12f);
    __nv_bfloat162* dst = (__nv_bfloat162*)(g_bf + (size_t)row * D);
    #pragma unroll
    for (int i = 0; i < 8; i++) {
        __nv_bfloat162 p0 = __nv_bfloat162(__float2bfloat16(v[i].x * scale),
                                           __float2bfloat16(v[i].y * scale));
        __nv_bfloat162 p1 = __nv_bfloat162(__float2bfloat16(v[i].z * scale),
                                           __float2bfloat16(v[i].w * scale));
        dst[(lane + 32 * i) * 2]     = p0;
        dst[(lane + 32 * i) * 2 + 1] = p1;
    }
}

// ---------------- kernel 2: 128x128 gram tile, 3-stage, one barrier/chunk ----------------
// (R10/R13 mainloop, unchanged — best measured config)
#define A_OFF 0
#define B_OFF 16384
#define STAGE_BYTES 32768
#define SMEM_TOTAL (NSTAGE * STAGE_BYTES)

__global__ void __launch_bounds__(256, 2) gram_kernel() {
    int tj = blockIdx.x;        // col tile
    int ti = blockIdx.y;        // row tile
    if (ti > tj) return;        // upper triangle only

    extern __shared__ char smem[];
    __shared__ unsigned s_rmax[BT], s_cmax[BT];

    const int rowBase = ti * BT;
    const int colBase = tj * BT;
    const int tid  = threadIdx.x;
    const int lane = tid & 31;
    const int wid  = tid >> 5;       // 0..7
    const int wm   = wid & 3;        // rows wm*32..+31
    const int wn   = wid >> 2;       // cols wn*64..+63

    if (tid < BT) { s_rmax[tid] = 0u; s_cmax[tid] = 0u; }

    uint32_t sb = smem_u32(smem);

    auto load_stage = [&](int kt, int s) {
        int k0 = kt * BK;
        uint32_t base = sb + s * STAGE_BYTES;
        #pragma unroll
        for (int it = 0; it < 4; it++) {
            int i = tid + it * 256;                        // 0..1023
            int r = i >> 3, seg = i & 7;
            uint32_t off = SW128(r * 128 + seg * 16);
            cp16(base + A_OFF + off, g_bf + (size_t)(rowBase + r) * D + k0 + seg * 8);
            cp16(base + B_OFF + off, g_bf + (size_t)(colBase + r) * D + k0 + seg * 8);
        }
        asm volatile("cp.async.commit_group;" ::: "memory");
    };

    float acc[2][8][4];
    #pragma unroll
    for (int mf = 0; mf < 2; mf++)
        #pragma unroll
        for (int nf = 0; nf < 8; nf++)
            #pragma unroll
            for (int e = 0; e < 4; e++) acc[mf][nf][e] = 0.0f;

    const int aRowL = (lane & 7) + ((lane >> 3) & 1) * 8;
    const int aColS = (lane >> 4) * 16;
    const int bRowL = (lane & 7) + (lane >> 4) * 8;
    const int bColS = ((lane >> 3) & 1) * 16;

    load_stage(0, 0);
    load_stage(1, 1);

    #pragma unroll 1
    for (int kt = 0; kt < NKT; kt++) {
        int s = kt % NSTAGE;
        if (kt == NKT - 1) asm volatile("cp.async.wait_group 0;" ::: "memory");
        else               asm volatile("cp.async.wait_group 1;" ::: "memory");
        __syncthreads();   // load kt visible; all warps past compute of kt-1
        if (kt + 2 < NKT) load_stage(kt + 2, (kt + 2) % NSTAGE);

        uint32_t aBase = sb + s * STAGE_BYTES + A_OFF;
        uint32_t bBase = sb + s * STAGE_BYTES + B_OFF;

        #pragma unroll
        for (int ks = 0; ks < 4; ks++) {
            int kb = ks * 32;
            uint32_t a[2][4], b[4][4];
            #pragma unroll
            for (int mf = 0; mf < 2; mf++) {
                int r = wm * 32 + mf * 16 + aRowL;
                ldm_x4(a[mf], aBase + SW128(r * 128 + kb + aColS));
            }
            #pragma unroll
            for (int np = 0; np < 4; np++) {
                int r = wn * 64 + np * 16 + bRowL;
                ldm_x4(b[np], bBase + SW128(r * 128 + kb + bColS));
            }
            #pragma unroll
            for (int mf = 0; mf < 2; mf++)
                #pragma unroll
                for (int np = 0; np < 4; np++) {
                    mma16816(acc[mf][2 * np],     a[mf], &b[np][0]);
                    mma16816(acc[mf][2 * np + 1], a[mf], &b[np][2]);
                }
        }
    }

    // ---- diagonal mask ----
    const int g  = lane >> 2;
    const int cq = lane & 3;
    if (ti == tj) {
        #pragma unroll
        for (int mf = 0; mf < 2; mf++)
            #pragma unroll
            for (int nf = 0; nf < 8; nf++)
                #pragma unroll
                for (int e = 0; e < 4; e++) {
                    int row = wm * 32 + mf * 16 + g + (e >> 1) * 8;
                    int col = wn * 64 + nf * 8 + 2 * cq + (e & 1);
                    if (row == col) acc[mf][nf][e] = -3.0f;
                }
    }

    // ---- row maxes ----
    #pragma unroll
    for (int mf = 0; mf < 2; mf++)
        #pragma unroll
        for (int h = 0; h < 2; h++) {
            float m = -3.0f;
            #pragma unroll
            for (int nf = 0; nf < 8; nf++) {
                m = fmaxf(m, acc[mf][nf][2 * h]);
                m = fmaxf(m, acc[mf][nf][2 * h + 1]);
            }
            m = fmaxf(m, __shfl_xor_sync(0xffffffffu, m, 1));
            m = fmaxf(m, __shfl_xor_sync(0xffffffffu, m, 2));
            if (cq == 0) atomicMax(&s_rmax[wm * 32 + mf * 16 + h * 8 + g], f2key(m));
        }

    // ---- col maxes ----
    #pragma unroll
    for (int nf = 0; nf < 8; nf++)
        #pragma unroll
        for (int e = 0; e < 2; e++) {
            float m = -3.0f;
            #pragma unroll
            for (int mf = 0; mf < 2; mf++) {
                m = fmaxf(m, acc[mf][nf][e]);
                m = fmaxf(m, acc[mf][nf][2 + e]);
            }
            m = fmaxf(m, __shfl_xor_sync(0xffffffffu, m, 4));
            m = fmaxf(m, __shfl_xor_sync(0xffffffffu, m, 8));
            m = fmaxf(m, __shfl_xor_sync(0xffffffffu, m, 16));
            if (g == 0) atomicMax(&s_cmax[wn * 64 + nf * 8 + 2 * cq + e], f2key(m));
        }
    __syncthreads();

    if (tid < BT) {
        atomicMax(&g_rowmax[rowBase + tid], s_rmax[tid]);
    } else {
        int c = tid - BT;
        if (ti != tj) atomicMax(&g_rowmax[colBase + c], s_cmax[c]);
    }
}

// ---------------- kernel 3a: parallel partial loss (64 blocks x 256 thr) ----------------
__global__ void loss_partial_kernel() {
    int i = blockIdx.x * 256 + threadIdx.x;      // one element per thread
    float md = key2f(g_rowmax[i]);
    float d2 = fmaxf(2.0f - 2.0f * md, 0.0f);
    float s  = logf(sqrtf(d2) + 1e-8f);
    __shared__ float red[8];
    #pragma unroll
    for (int o = 16; o > 0; o >>= 1) s += __shfl_xor_sync(0xffffffffu, s, o);
    if ((threadIdx.x & 31) == 0) red[threadIdx.x >> 5] = s;
    __syncthreads();
    if (threadIdx.x < 8) {
        float t = red[threadIdx.x];
        #pragma unroll
        for (int o = 4; o > 0; o >>= 1) t += __shfl_xor_sync(0xffu, t, o);
        if (threadIdx.x == 0) g_part[blockIdx.x] = t;
    }
}

// ---------------- kernel 3b: final reduce (1 block, 64 thr) ----------------
__global__ void loss_final_kernel(float* __restrict__ out) {
    float s = g_part[threadIdx.x];
    #pragma unroll
    for (int o = 16; o > 0; o >>= 1) s += __shfl_xor_sync(0xffffffffu, s, o);
    __shared__ float red[2];
    if ((threadIdx.x & 31) == 0) red[threadIdx.x >> 5] = s;
    __syncthreads();
    if (threadIdx.x == 0) out[0] = -(red[0] + red[1]) / (float)N;
}

// ---------------- launch ----------------
extern "C" void kernel_launch(void* const* d_in, const int* in_sizes, int n_in,
                              void* d_out, int out_size) {
    const float* feats = (const float*)d_in[0];
    float* out = (float*)d_out;

    cudaFuncSetAttribute(gram_kernel, cudaFuncAttributeMaxDynamicSharedMemorySize, SMEM_TOTAL);

    normalize_kernel<<<N / 8, 256>>>(feats);
    dim3 grid(N / BT, N / BT);          // (128,128); ti>tj exits immediately
    gram_kernel<<<grid, 256, SMEM_TOTAL>>>();
    loss_partial_kernel<<<64, 256>>>();
    loss_final_kernel<<<1, 64>>>(out);
}